// round 3
// baseline (speedup 1.0000x reference)
#include <cuda_runtime.h>
#include <cstdint>

#define NTH 1024
#define KTOP 500
#define CAND_MAX 4096
#define NBIN 4096
#define NTASK 336

struct Smem {
    union {
        struct { unsigned int hist[NBIN]; unsigned int scan[NTH]; } h;  // fallback only
        unsigned long long cand[CAND_MAX];                              // 32 KB
    } u;
    float4 bx4[512];                          // 8 KB
    unsigned long long sup[KTOP][8];          // 32 KB
    unsigned long long keepw[8];
    int T, cntAbove, cnt;
};

__device__ __forceinline__ unsigned int mapf(float v) {
    unsigned int u = __float_as_uint(v);
    return (u & 0x80000000u) ? ~u : (u | 0x80000000u);
}
__device__ __forceinline__ float unmapf(unsigned int u) {
    return __uint_as_float((u & 0x80000000u) ? (u ^ 0x80000000u) : ~u);
}

__device__ void find_thr(Smem& S, int need, int tid, int& T_out, int& above_out) {
    int t4 = tid * 4;
    unsigned h0 = S.u.h.hist[t4], h1 = S.u.h.hist[t4 + 1];
    unsigned h2 = S.u.h.hist[t4 + 2], h3 = S.u.h.hist[t4 + 3];
    S.u.h.scan[tid] = h0 + h1 + h2 + h3;
    __syncthreads();
    for (int off = 1; off < NTH; off <<= 1) {
        unsigned add = (tid + off < NTH) ? S.u.h.scan[tid + off] : 0u;
        __syncthreads();
        S.u.h.scan[tid] += add;
        __syncthreads();
    }
    unsigned sfx = S.u.h.scan[tid];
    unsigned nxt = (tid < NTH - 1) ? S.u.h.scan[tid + 1] : 0u;
    if (sfx >= (unsigned)need && nxt < (unsigned)need) {
        unsigned c = nxt;
        unsigned hh[4] = { h0, h1, h2, h3 };
        for (int b = 3; b >= 0; b--) {
            if (c + hh[b] >= (unsigned)need) { S.T = t4 + b; S.cntAbove = (int)c; break; }
            c += hh[b];
        }
    }
    __syncthreads();
    T_out = S.T;
    above_out = S.cntAbove;
}

// process one float4 of logits; accept elements > thf
__device__ __forceinline__ void scan4(Smem& S, float4 v, float thf, int i4, int a) {
    float mx = fmaxf(fmaxf(v.x, v.y), fmaxf(v.z, v.w));
    if (mx > thf) {
        float f[4] = { v.x, v.y, v.z, v.w };
        #pragma unroll
        for (int e = 0; e < 4; e++) {
            if (f[e] > thf) {
                int pos = atomicAdd(&S.cnt, 1);
                if (pos < CAND_MAX) {
                    unsigned n = (unsigned)((i4 * 4 + e) * 3 + a);
                    S.u.cand[pos] = ((unsigned long long)mapf(f[e]) << 32)
                                  | (unsigned long long)(~n);
                }
            }
        }
    }
}

__global__ __launch_bounds__(NTH, 2) void retina_kernel(
    const float* __restrict__ cls3, const float* __restrict__ cls4, const float* __restrict__ cls5,
    const float* __restrict__ reg3, const float* __restrict__ reg4, const float* __restrict__ reg5,
    float* __restrict__ out)
{
    extern __shared__ unsigned char smem_raw[];
    Smem& S = *reinterpret_cast<Smem*>(smem_raw);
    const int tid = threadIdx.x;
    const int lane = tid & 31;

    // spread heavy/light levels across SMs: consecutive blocks cycle lev 0,1,2
    int bid = blockIdx.x;
    int task = (bid % 3) * 112 + bid / 3;
    int lev = (task < 112) ? 0 : ((task < 224) ? 1 : 2);
    int tt  = task - lev * 112;
    int img = tt / 7;
    int cls = tt % 7;

    const int H = 192 >> lev;
    const int W = H;
    const int HW = H * W;
    const float stride = (float)(8 << lev);
    const float asize  = (float)(16 << lev);

    const float* clsP = (lev == 0) ? cls3 : ((lev == 1) ? cls4 : cls5);
    const float* regP = (lev == 0) ? reg3 : ((lev == 1) ? reg4 : reg5);

    const float* plane0 = clsP + (size_t)(img * 24 + 0 * 8 + cls + 1) * HW;
    const float* plane1 = clsP + (size_t)(img * 24 + 1 * 8 + cls + 1) * HW;
    const float* plane2 = clsP + (size_t)(img * 24 + 2 * 8 + cls + 1) * HW;

    if (tid == 0) S.cnt = 0;
    if (tid < 8) S.keepw[tid] = 0ull;
    __syncthreads();

    // ---------- fast path: single-pass threshold compaction ----------
    float thf = (lev == 0) ? -1.55f : ((lev == 1) ? -2.10f : -2.80f);

    {
        const float4* p0 = (const float4*)plane0;
        const float4* p1 = (const float4*)plane1;
        const float4* p2 = (const float4*)plane2;
        int nv4 = HW >> 2;
        for (int i4 = tid; i4 < nv4; i4 += NTH) {
            float4 v0 = p0[i4];
            float4 v1 = p1[i4];
            float4 v2 = p2[i4];
            scan4(S, v0, thf, i4, 0);
            scan4(S, v1, thf, i4, 1);
            scan4(S, v2, thf, i4, 2);
        }
    }
    __syncthreads();
    int cnt = S.cnt;

    // ---------- exact fallback: 12-bit histogram select (rare) ----------
    if (cnt < KTOP || cnt > CAND_MAX) {
        const float* planes[3] = { plane0, plane1, plane2 };
        for (int i = tid; i < NBIN; i += NTH) S.u.h.hist[i] = 0;
        __syncthreads();
        for (int a = 0; a < 3; a++) {
            const float* p = planes[a];
            for (int i = tid; i < HW; i += NTH) {
                unsigned u = mapf(p[i]);
                int bin = (int)(u >> 20);
                unsigned m = __match_any_sync(__activemask(), bin);
                int leader = __ffs(m) - 1;
                if (lane == leader) atomicAdd(&S.u.h.hist[bin], (unsigned)__popc(m));
            }
        }
        __syncthreads();
        int T, above;
        find_thr(S, KTOP, tid, T, above);
        if (tid == 0) S.cnt = 0;
        __syncthreads();
        for (int a = 0; a < 3; a++) {
            const float* p = planes[a];
            for (int i = tid; i < HW; i += NTH) {
                unsigned u = mapf(p[i]);
                if ((int)(u >> 20) >= T) {
                    int pos = atomicAdd(&S.cnt, 1);
                    if (pos < CAND_MAX) {
                        unsigned n = (unsigned)(i * 3 + a);
                        S.u.cand[pos] = ((unsigned long long)u << 32) | (unsigned long long)(~n);
                    }
                }
            }
        }
        __syncthreads();
        cnt = S.cnt;

        if (cnt > CAND_MAX) {
            for (int i = tid; i < NBIN; i += NTH) S.u.h.hist[i] = 0;
            __syncthreads();
            for (int a = 0; a < 3; a++) {
                const float* p = planes[a];
                for (int i = tid; i < HW; i += NTH) {
                    unsigned u = mapf(p[i]);
                    if ((int)(u >> 20) == T)
                        atomicAdd(&S.u.h.hist[(u >> 8) & 0xFFFu], 1u);
                }
            }
            __syncthreads();
            int T2, ab2;
            find_thr(S, KTOP - above, tid, T2, ab2);
            if (tid == 0) S.cnt = 0;
            __syncthreads();
            for (int a = 0; a < 3; a++) {
                const float* p = planes[a];
                for (int i = tid; i < HW; i += NTH) {
                    unsigned u = mapf(p[i]);
                    int bin = (int)(u >> 20);
                    if (bin > T || (bin == T && (int)((u >> 8) & 0xFFFu) >= T2)) {
                        int pos = atomicAdd(&S.cnt, 1);
                        if (pos < CAND_MAX) {
                            unsigned n = (unsigned)(i * 3 + a);
                            S.u.cand[pos] = ((unsigned long long)u << 32) | (unsigned long long)(~n);
                        }
                    }
                }
            }
            __syncthreads();
            cnt = S.cnt;
        }
    }
    if (cnt > CAND_MAX) cnt = CAND_MAX;

    // ---------- sort descending ----------
    if (cnt <= 1024) {
        // register bitonic, 1 elem/thread; j<32 via shfl, j>=32 via smem
        unsigned long long v = (tid < cnt) ? S.u.cand[tid] : 0ull;
        const int i = tid;
        for (int k = 2; k <= 1024; k <<= 1) {
            for (int j = k >> 1; j > 0; j >>= 1) {
                unsigned long long v2;
                if (j >= 32) {
                    __syncthreads();
                    S.u.cand[i] = v;
                    __syncthreads();
                    v2 = S.u.cand[i ^ j];
                } else {
                    v2 = __shfl_xor_sync(0xFFFFFFFFu, v, j);
                }
                bool ilt = ((i & j) == 0);
                bool wantmax = (((i & k) == 0) == ilt);
                v = wantmax ? (v > v2 ? v : v2) : (v < v2 ? v : v2);
            }
        }
        __syncthreads();
        S.u.cand[i] = v;
        __syncthreads();
    } else {
        int M = 2048;
        while (M < cnt) M <<= 1;
        for (int i = cnt + tid; i < M; i += NTH) S.u.cand[i] = 0ull;
        __syncthreads();
        for (int k = 2; k <= M; k <<= 1) {
            for (int j = k >> 1; j > 0; j >>= 1) {
                for (int i = tid; i < M; i += NTH) {
                    int ixj = i ^ j;
                    if (ixj > i) {
                        unsigned long long a = S.u.cand[i], b = S.u.cand[ixj];
                        bool sw = ((i & k) == 0) ? (a < b) : (a > b);
                        if (sw) { S.u.cand[i] = b; S.u.cand[ixj] = a; }
                    }
                }
                __syncthreads();
            }
        }
    }

    // ---------- decode top-500, write boxes/scores/labels ----------
    long long tbase = (long long)((lev * 16 + img) * 7 + cls) * KTOP;
    float4* obox4 = (float4*)(out + tbase * 4);
    float* osc   = out + 672000 + tbase;
    float* okeep = out + 840000 + tbase;
    float* olab  = out + 1008000 + tbase;

    if (tid < 512) {
        int r = tid;
        bool valid_bit = false;
        if (r < KTOP) {
            unsigned long long key = S.u.cand[r];
            unsigned u = (unsigned)(key >> 32);
            unsigned n = ~((unsigned)key);
            float logit = unmapf(u);
            float score = __fdividef(1.0f, 1.0f + __expf(-logit));

            int a = (int)(n % 3u);
            int p = (int)(n / 3u);
            int x = p % W;
            int y = p / W;
            float sqv = (a == 0) ? 0.70710678118654752f : ((a == 1) ? 1.0f : 1.41421356237309505f);
            float wa = asize * sqv;
            float ha = asize / sqv;
            float cxa = ((float)x + 0.5f) * stride;
            float cya = ((float)y + 0.5f) * stride;

            size_t rb = (size_t)(img * 12 + a * 4) * HW + (size_t)p;
            float dx = regP[rb];
            float dy = regP[rb + HW];
            float dw = regP[rb + 2 * (size_t)HW];
            float dh = regP[rb + 3 * (size_t)HW];

            float cx = dx * wa + cxa;
            float cy = dy * ha + cya;
            float bw = __expf(dw) * wa;
            float bh = __expf(dh) * ha;
            float bx1 = cx - 0.5f * bw, by1 = cy - 0.5f * bh;
            float bx2 = cx + 0.5f * bw, by2 = cy + 0.5f * bh;

            S.bx4[r] = make_float4(bx1, by1, bx2, by2);
            obox4[r] = make_float4(bx1, by1, bx2, by2);
            osc[r] = score;
            olab[r] = (float)cls;
            valid_bit = (score > 0.05f);
        } else {
            S.bx4[r] = make_float4(1e30f, 1e30f, 1e30f, 1e30f);
        }
        unsigned b = __ballot_sync(0xFFFFFFFFu, valid_bit);
        if (lane == 0 && b)
            atomicOr(&S.keepw[r >> 6], (unsigned long long)b << ((r >> 5 & 1) * 32));
    }
    __syncthreads();

    // ---------- suppression bitmask matrix: warp-tiled 32x64, j-broadcast ----------
    {
        int warpId = tid >> 5;
        for (int t = warpId; t < 128; t += 32) {
            int tr = t >> 3, w = t & 7;
            int r0 = tr << 5;
            if (w * 64 + 63 <= r0) continue;      // tile entirely j<=i: never used
            int i = r0 + lane;
            float4 bi = S.bx4[i];
            float ai = (bi.z - bi.x) * (bi.w - bi.y);
            unsigned long long bits = 0ull;
            int jb = w << 6;
            #pragma unroll 4
            for (int b = 0; b < 64; b++) {
                float4 bj = S.bx4[jb + b];        // broadcast load
                float xx1 = fmaxf(bi.x, bj.x);
                float yy1 = fmaxf(bi.y, bj.y);
                float xx2 = fminf(bi.z, bj.z);
                float yy2 = fminf(bi.w, bj.w);
                float inter = fmaxf(xx2 - xx1, 0.0f) * fmaxf(yy2 - yy1, 0.0f);
                float aj = (bj.z - bj.x) * (bj.w - bj.y);
                float uni = fmaxf(ai + aj - inter, 1e-9f);
                if (inter > 0.5f * uni) bits |= (1ull << b);
            }
            if (i < KTOP) S.sup[i][w] = bits;
        }
    }
    __syncthreads();

    // ---------- greedy NMS: warp 0, chunk-prefetched serial + parallel cross-word ----------
    if (tid < 32) {
        for (int w = 0; w < 8; w++) {
            if (lane == 0) {
                // within-word greedy on snapshot with 4-wide suppression-row prefetch
                unsigned long long snap = S.keepw[w];
                unsigned long long supm = 0ull, kept = 0ull, rem = snap;
                int base = w << 6;
                while (rem) {
                    int b0, b1 = -1, b2 = -1, b3 = -1;
                    unsigned long long s0, s1 = 0, s2 = 0, s3 = 0;
                    b0 = __ffsll((long long)rem) - 1; rem &= rem - 1;
                    s0 = S.sup[base + b0][w];
                    if (rem) { b1 = __ffsll((long long)rem) - 1; rem &= rem - 1; s1 = S.sup[base + b1][w]; }
                    if (rem) { b2 = __ffsll((long long)rem) - 1; rem &= rem - 1; s2 = S.sup[base + b2][w]; }
                    if (rem) { b3 = __ffsll((long long)rem) - 1; rem &= rem - 1; s3 = S.sup[base + b3][w]; }
                    if (!((supm >> b0) & 1ull)) { kept |= 1ull << b0; supm |= s0; }
                    if (b1 >= 0 && !((supm >> b1) & 1ull)) { kept |= 1ull << b1; supm |= s1; }
                    if (b2 >= 0 && !((supm >> b2) & 1ull)) { kept |= 1ull << b2; supm |= s2; }
                    if (b3 >= 0 && !((supm >> b3) & 1ull)) { kept |= 1ull << b3; supm |= s3; }
                }
                S.keepw[w] = kept;
            }
            __syncwarp();
            // cross-word: lane t clears suppressions in word w+1+t from kept rows of word w
            int w2 = w + 1 + lane;
            if (lane < 7 && w2 < 8) {
                unsigned long long kept = S.keepw[w];
                unsigned long long acc = 0ull;
                int base = w << 6;
                while (kept) {
                    int b = __ffsll((long long)kept) - 1; kept &= kept - 1;
                    acc |= S.sup[base + b][w2];
                }
                S.keepw[w2] &= ~acc;
            }
            __syncwarp();
        }
    }
    __syncthreads();

    for (int r = tid; r < KTOP; r += NTH)
        okeep[r] = ((S.keepw[r >> 6] >> (r & 63)) & 1ull) ? 1.0f : 0.0f;
}

extern "C" void kernel_launch(void* const* d_in, const int* in_sizes, int n_in,
                              void* d_out, int out_size) {
    const float *cls3 = nullptr, *cls4 = nullptr, *cls5 = nullptr;
    const float *reg3 = nullptr, *reg4 = nullptr, *reg5 = nullptr;
    for (int i = 0; i < n_in; i++) {
        switch (in_sizes[i]) {
            case 14155776: cls3 = (const float*)d_in[i]; break;
            case 7077888:  reg3 = (const float*)d_in[i]; break;
            case 3538944:  cls4 = (const float*)d_in[i]; break;
            case 1769472:  reg4 = (const float*)d_in[i]; break;
            case 884736:   cls5 = (const float*)d_in[i]; break;
            case 442368:   reg5 = (const float*)d_in[i]; break;
        }
    }
    cudaFuncSetAttribute(retina_kernel, cudaFuncAttributeMaxDynamicSharedMemorySize,
                         (int)sizeof(Smem));
    retina_kernel<<<NTASK, NTH, sizeof(Smem)>>>(cls3, cls4, cls5, reg3, reg4, reg5,
                                                (float*)d_out);
}

// round 4
// speedup vs baseline: 1.0376x; 1.0376x over previous
#include <cuda_runtime.h>
#include <cstdint>

#define NTH 1024
#define KTOP 500
#define CAND_MAX 4096
#define NBIN 4096
#define NTASK 336

struct Smem {
    union {
        struct { unsigned int hist[NBIN]; unsigned int scan[NTH]; } h;  // fallback only
        unsigned long long cand[CAND_MAX];                              // 32 KB
    } u;
    float4 bx4[512];                          // 8 KB
    unsigned long long sup[KTOP][8];          // 32 KB
    unsigned long long keepw[8];
    int T, cntAbove, cnt;
};

__device__ __forceinline__ unsigned int mapf(float v) {
    unsigned int u = __float_as_uint(v);
    return (u & 0x80000000u) ? ~u : (u | 0x80000000u);
}
__device__ __forceinline__ float unmapf(unsigned int u) {
    return __uint_as_float((u & 0x80000000u) ? (u ^ 0x80000000u) : ~u);
}

__device__ void find_thr(Smem& S, int need, int tid, int& T_out, int& above_out) {
    int t4 = tid * 4;
    unsigned h0 = S.u.h.hist[t4], h1 = S.u.h.hist[t4 + 1];
    unsigned h2 = S.u.h.hist[t4 + 2], h3 = S.u.h.hist[t4 + 3];
    S.u.h.scan[tid] = h0 + h1 + h2 + h3;
    __syncthreads();
    for (int off = 1; off < NTH; off <<= 1) {
        unsigned add = (tid + off < NTH) ? S.u.h.scan[tid + off] : 0u;
        __syncthreads();
        S.u.h.scan[tid] += add;
        __syncthreads();
    }
    unsigned sfx = S.u.h.scan[tid];
    unsigned nxt = (tid < NTH - 1) ? S.u.h.scan[tid + 1] : 0u;
    if (sfx >= (unsigned)need && nxt < (unsigned)need) {
        unsigned c = nxt;
        unsigned hh[4] = { h0, h1, h2, h3 };
        for (int b = 3; b >= 0; b--) {
            if (c + hh[b] >= (unsigned)need) { S.T = t4 + b; S.cntAbove = (int)c; break; }
            c += hh[b];
        }
    }
    __syncthreads();
    T_out = S.T;
    above_out = S.cntAbove;
}

// process one float4 of logits; accept elements > thf
__device__ __forceinline__ void scan4(Smem& S, float4 v, float thf, int i4, int a) {
    float mx = fmaxf(fmaxf(v.x, v.y), fmaxf(v.z, v.w));
    if (mx > thf) {
        float f[4] = { v.x, v.y, v.z, v.w };
        #pragma unroll
        for (int e = 0; e < 4; e++) {
            if (f[e] > thf) {
                int pos = atomicAdd(&S.cnt, 1);
                if (pos < CAND_MAX) {
                    unsigned n = (unsigned)((i4 * 4 + e) * 3 + a);
                    S.u.cand[pos] = ((unsigned long long)mapf(f[e]) << 32)
                                  | (unsigned long long)(~n);
                }
            }
        }
    }
}

__global__ __launch_bounds__(NTH, 2) void retina_kernel(
    const float* __restrict__ cls3, const float* __restrict__ cls4, const float* __restrict__ cls5,
    const float* __restrict__ reg3, const float* __restrict__ reg4, const float* __restrict__ reg5,
    float* __restrict__ out)
{
    extern __shared__ unsigned char smem_raw[];
    Smem& S = *reinterpret_cast<Smem*>(smem_raw);
    const int tid = threadIdx.x;
    const int lane = tid & 31;

    // identity task order: heavy lev0 tasks launch first, cheap lev2 fill the tail wave
    int task = blockIdx.x;
    int lev = (task < 112) ? 0 : ((task < 224) ? 1 : 2);
    int tt  = task - lev * 112;
    int img = tt / 7;
    int cls = tt % 7;

    const int H = 192 >> lev;
    const int W = H;
    const int HW = H * W;
    const float stride = (float)(8 << lev);
    const float asize  = (float)(16 << lev);

    const float* clsP = (lev == 0) ? cls3 : ((lev == 1) ? cls4 : cls5);
    const float* regP = (lev == 0) ? reg3 : ((lev == 1) ? reg4 : reg5);

    const float* plane0 = clsP + (size_t)(img * 24 + 0 * 8 + cls + 1) * HW;
    const float* plane1 = clsP + (size_t)(img * 24 + 1 * 8 + cls + 1) * HW;
    const float* plane2 = clsP + (size_t)(img * 24 + 2 * 8 + cls + 1) * HW;

    if (tid == 0) S.cnt = 0;
    if (tid < 8) S.keepw[tid] = 0ull;
    __syncthreads();

    // ---------- fast path: single-pass threshold compaction ----------
    float thf = (lev == 0) ? -1.55f : ((lev == 1) ? -2.10f : -2.80f);

    {
        const float4* p0 = (const float4*)plane0;
        const float4* p1 = (const float4*)plane1;
        const float4* p2 = (const float4*)plane2;
        int nv4 = HW >> 2;
        for (int i4 = tid; i4 < nv4; i4 += NTH) {
            float4 v0 = p0[i4];
            float4 v1 = p1[i4];
            float4 v2 = p2[i4];
            scan4(S, v0, thf, i4, 0);
            scan4(S, v1, thf, i4, 1);
            scan4(S, v2, thf, i4, 2);
        }
    }
    __syncthreads();
    int cnt = S.cnt;

    // ---------- exact fallback: 12-bit histogram select (rare) ----------
    if (cnt < KTOP || cnt > CAND_MAX) {
        const float* planes[3] = { plane0, plane1, plane2 };
        for (int i = tid; i < NBIN; i += NTH) S.u.h.hist[i] = 0;
        __syncthreads();
        for (int a = 0; a < 3; a++) {
            const float* p = planes[a];
            for (int i = tid; i < HW; i += NTH) {
                unsigned u = mapf(p[i]);
                int bin = (int)(u >> 20);
                unsigned m = __match_any_sync(__activemask(), bin);
                int leader = __ffs(m) - 1;
                if (lane == leader) atomicAdd(&S.u.h.hist[bin], (unsigned)__popc(m));
            }
        }
        __syncthreads();
        int T, above;
        find_thr(S, KTOP, tid, T, above);
        if (tid == 0) S.cnt = 0;
        __syncthreads();
        for (int a = 0; a < 3; a++) {
            const float* p = planes[a];
            for (int i = tid; i < HW; i += NTH) {
                unsigned u = mapf(p[i]);
                if ((int)(u >> 20) >= T) {
                    int pos = atomicAdd(&S.cnt, 1);
                    if (pos < CAND_MAX) {
                        unsigned n = (unsigned)(i * 3 + a);
                        S.u.cand[pos] = ((unsigned long long)u << 32) | (unsigned long long)(~n);
                    }
                }
            }
        }
        __syncthreads();
        cnt = S.cnt;

        if (cnt > CAND_MAX) {
            for (int i = tid; i < NBIN; i += NTH) S.u.h.hist[i] = 0;
            __syncthreads();
            for (int a = 0; a < 3; a++) {
                const float* p = planes[a];
                for (int i = tid; i < HW; i += NTH) {
                    unsigned u = mapf(p[i]);
                    if ((int)(u >> 20) == T)
                        atomicAdd(&S.u.h.hist[(u >> 8) & 0xFFFu], 1u);
                }
            }
            __syncthreads();
            int T2, ab2;
            find_thr(S, KTOP - above, tid, T2, ab2);
            if (tid == 0) S.cnt = 0;
            __syncthreads();
            for (int a = 0; a < 3; a++) {
                const float* p = planes[a];
                for (int i = tid; i < HW; i += NTH) {
                    unsigned u = mapf(p[i]);
                    int bin = (int)(u >> 20);
                    if (bin > T || (bin == T && (int)((u >> 8) & 0xFFFu) >= T2)) {
                        int pos = atomicAdd(&S.cnt, 1);
                        if (pos < CAND_MAX) {
                            unsigned n = (unsigned)(i * 3 + a);
                            S.u.cand[pos] = ((unsigned long long)u << 32) | (unsigned long long)(~n);
                        }
                    }
                }
            }
            __syncthreads();
            cnt = S.cnt;
        }
    }
    if (cnt > CAND_MAX) cnt = CAND_MAX;

    // ---------- sort descending ----------
    if (cnt <= 1024) {
        // register bitonic, 1 elem/thread; j<32 via shfl, j>=32 via smem
        unsigned long long v = (tid < cnt) ? S.u.cand[tid] : 0ull;
        const int i = tid;
        for (int k = 2; k <= 1024; k <<= 1) {
            for (int j = k >> 1; j > 0; j >>= 1) {
                unsigned long long v2;
                if (j >= 32) {
                    __syncthreads();
                    S.u.cand[i] = v;
                    __syncthreads();
                    v2 = S.u.cand[i ^ j];
                } else {
                    v2 = __shfl_xor_sync(0xFFFFFFFFu, v, j);
                }
                bool ilt = ((i & j) == 0);
                bool wantmax = (((i & k) == 0) == ilt);
                v = wantmax ? (v > v2 ? v : v2) : (v < v2 ? v : v2);
            }
        }
        __syncthreads();
        S.u.cand[i] = v;
        __syncthreads();
    } else {
        int M = 2048;
        while (M < cnt) M <<= 1;
        for (int i = cnt + tid; i < M; i += NTH) S.u.cand[i] = 0ull;
        __syncthreads();
        for (int k = 2; k <= M; k <<= 1) {
            for (int j = k >> 1; j > 0; j >>= 1) {
                for (int i = tid; i < M; i += NTH) {
                    int ixj = i ^ j;
                    if (ixj > i) {
                        unsigned long long a = S.u.cand[i], b = S.u.cand[ixj];
                        bool sw = ((i & k) == 0) ? (a < b) : (a > b);
                        if (sw) { S.u.cand[i] = b; S.u.cand[ixj] = a; }
                    }
                }
                __syncthreads();
            }
        }
    }

    // ---------- decode top-500, write boxes/scores/labels ----------
    long long tbase = (long long)((lev * 16 + img) * 7 + cls) * KTOP;
    float4* obox4 = (float4*)(out + tbase * 4);
    float* osc   = out + 672000 + tbase;
    float* okeep = out + 840000 + tbase;
    float* olab  = out + 1008000 + tbase;

    if (tid < 512) {
        int r = tid;
        bool valid_bit = false;
        if (r < KTOP) {
            unsigned long long key = S.u.cand[r];
            unsigned u = (unsigned)(key >> 32);
            unsigned n = ~((unsigned)key);
            float logit = unmapf(u);
            float score = __fdividef(1.0f, 1.0f + __expf(-logit));

            int a = (int)(n % 3u);
            int p = (int)(n / 3u);
            int x = p % W;
            int y = p / W;
            float sqv = (a == 0) ? 0.70710678118654752f : ((a == 1) ? 1.0f : 1.41421356237309505f);
            float wa = asize * sqv;
            float ha = asize / sqv;
            float cxa = ((float)x + 0.5f) * stride;
            float cya = ((float)y + 0.5f) * stride;

            size_t rb = (size_t)(img * 12 + a * 4) * HW + (size_t)p;
            float dx = regP[rb];
            float dy = regP[rb + HW];
            float dw = regP[rb + 2 * (size_t)HW];
            float dh = regP[rb + 3 * (size_t)HW];

            float cx = dx * wa + cxa;
            float cy = dy * ha + cya;
            float bw = __expf(dw) * wa;
            float bh = __expf(dh) * ha;
            float bx1 = cx - 0.5f * bw, by1 = cy - 0.5f * bh;
            float bx2 = cx + 0.5f * bw, by2 = cy + 0.5f * bh;

            S.bx4[r] = make_float4(bx1, by1, bx2, by2);
            obox4[r] = make_float4(bx1, by1, bx2, by2);
            osc[r] = score;
            olab[r] = (float)cls;
            valid_bit = (score > 0.05f);
        } else {
            S.bx4[r] = make_float4(1e30f, 1e30f, 1e30f, 1e30f);
        }
        unsigned b = __ballot_sync(0xFFFFFFFFu, valid_bit);
        if (lane == 0 && b)
            atomicOr(&S.keepw[r >> 6], (unsigned long long)b << ((r >> 5 & 1) * 32));
    }
    __syncthreads();

    // ---------- suppression bitmask matrix: warp-tiled 32x64, j-broadcast ----------
    {
        int warpId = tid >> 5;
        for (int t = warpId; t < 128; t += 32) {
            int tr = t >> 3, w = t & 7;
            int r0 = tr << 5;
            if (w * 64 + 63 <= r0) continue;      // tile entirely j<=i: never used
            int i = r0 + lane;
            float4 bi = S.bx4[i];
            float ai = (bi.z - bi.x) * (bi.w - bi.y);
            unsigned long long bits = 0ull;
            int jb = w << 6;
            #pragma unroll 4
            for (int b = 0; b < 64; b++) {
                float4 bj = S.bx4[jb + b];        // broadcast load
                float xx1 = fmaxf(bi.x, bj.x);
                float yy1 = fmaxf(bi.y, bj.y);
                float xx2 = fminf(bi.z, bj.z);
                float yy2 = fminf(bi.w, bj.w);
                float inter = fmaxf(xx2 - xx1, 0.0f) * fmaxf(yy2 - yy1, 0.0f);
                float aj = (bj.z - bj.x) * (bj.w - bj.y);
                float uni = fmaxf(ai + aj - inter, 1e-9f);
                if (inter > 0.5f * uni) bits |= (1ull << b);
            }
            if (i < KTOP) S.sup[i][w] = bits;
        }
    }
    __syncthreads();

    // ---------- greedy NMS: warp 0, chunk-prefetched serial + parallel cross-word ----------
    if (tid < 32) {
        for (int w = 0; w < 8; w++) {
            if (lane == 0) {
                unsigned long long snap = S.keepw[w];
                unsigned long long supm = 0ull, kept = 0ull, rem = snap;
                int base = w << 6;
                while (rem) {
                    int b0, b1 = -1, b2 = -1, b3 = -1;
                    unsigned long long s0, s1 = 0, s2 = 0, s3 = 0;
                    b0 = __ffsll((long long)rem) - 1; rem &= rem - 1;
                    s0 = S.sup[base + b0][w];
                    if (rem) { b1 = __ffsll((long long)rem) - 1; rem &= rem - 1; s1 = S.sup[base + b1][w]; }
                    if (rem) { b2 = __ffsll((long long)rem) - 1; rem &= rem - 1; s2 = S.sup[base + b2][w]; }
                    if (rem) { b3 = __ffsll((long long)rem) - 1; rem &= rem - 1; s3 = S.sup[base + b3][w]; }
                    if (!((supm >> b0) & 1ull)) { kept |= 1ull << b0; supm |= s0; }
                    if (b1 >= 0 && !((supm >> b1) & 1ull)) { kept |= 1ull << b1; supm |= s1; }
                    if (b2 >= 0 && !((supm >> b2) & 1ull)) { kept |= 1ull << b2; supm |= s2; }
                    if (b3 >= 0 && !((supm >> b3) & 1ull)) { kept |= 1ull << b3; supm |= s3; }
                }
                S.keepw[w] = kept;
            }
            __syncwarp();
            int w2 = w + 1 + lane;
            if (lane < 7 && w2 < 8) {
                unsigned long long kept = S.keepw[w];
                unsigned long long acc = 0ull;
                int base = w << 6;
                while (kept) {
                    int b = __ffsll((long long)kept) - 1; kept &= kept - 1;
                    acc |= S.sup[base + b][w2];
                }
                S.keepw[w2] &= ~acc;
            }
            __syncwarp();
        }
    }
    __syncthreads();

    for (int r = tid; r < KTOP; r += NTH)
        okeep[r] = ((S.keepw[r >> 6] >> (r & 63)) & 1ull) ? 1.0f : 0.0f;
}

extern "C" void kernel_launch(void* const* d_in, const int* in_sizes, int n_in,
                              void* d_out, int out_size) {
    const float *cls3 = nullptr, *cls4 = nullptr, *cls5 = nullptr;
    const float *reg3 = nullptr, *reg4 = nullptr, *reg5 = nullptr;
    for (int i = 0; i < n_in; i++) {
        switch (in_sizes[i]) {
            case 14155776: cls3 = (const float*)d_in[i]; break;
            case 7077888:  reg3 = (const float*)d_in[i]; break;
            case 3538944:  cls4 = (const float*)d_in[i]; break;
            case 1769472:  reg4 = (const float*)d_in[i]; break;
            case 884736:   cls5 = (const float*)d_in[i]; break;
            case 442368:   reg5 = (const float*)d_in[i]; break;
        }
    }
    cudaFuncSetAttribute(retina_kernel, cudaFuncAttributeMaxDynamicSharedMemorySize,
                         (int)sizeof(Smem));
    retina_kernel<<<NTASK, NTH, sizeof(Smem)>>>(cls3, cls4, cls5, reg3, reg4, reg5,
                                                (float*)d_out);
}